// round 14
// baseline (speedup 1.0000x reference)
#include <cuda_runtime.h>
#include <cuda_bf16.h>
#include <mma.h>

using namespace nvcuda;

// Problem constants (fixed shapes per reference)
#define NN  100000
#define NE  1600000
#define NG  64
#define DIN 128
#define DH  256
#define PCH 16   // pool chunks per graph

// ---------------- scratch (device globals; no allocation anywhere) ----------
__device__ __align__(16) __nv_bfloat16 g_hA[(size_t)NN * DH];  // 51.2 MB
__device__ __align__(16) __nv_bfloat16 g_hB[(size_t)NN * DH];  // 51.2 MB
__device__ __align__(16) __nv_bfloat16 g_W1h[DIN * DH], g_W1l[DIN * DH];  // 64 KB each
__device__ __align__(16) __nv_bfloat16 g_W2h[DH * DH],  g_W2l[DH * DH];   // 128 KB each
__device__ float g_dinv[NN];
__device__ int   g_deg[NN];
__device__ int   g_rowptr[NN + 1];
__device__ int   g_cursor[NN];
__device__ int   g_src[NE];
__device__ float g_w[NE];
__device__ int   g_gstart[NG + 1];
__device__ float g_pp[NG * PCH * DH];       // pool partials (1 MB)

// ---------------- CSR build ----------------
__global__ void k_zero_deg() {
    int i = blockIdx.x * 256 + threadIdx.x;
    if (i < NN) g_deg[i] = 0;
}

__global__ void k_count(const int* __restrict__ col) {
    int e = blockIdx.x * 256 + threadIdx.x;
    if (e < NE) atomicAdd(&g_deg[col[e]], 1);
}

// Single-block exclusive scan over degrees -> rowptr, cursor. (int work ONLY:
// rsqrtf here would serialize 100K MUFU ops onto one SM — measured +55us.)
__global__ void k_scan() {
    __shared__ int sums[1024];
    int t = threadIdx.x;
    const int C = (NN + 1023) / 1024;  // 98
    int base = t * C, s = 0;
    for (int i = 0; i < C; i++) {
        int idx = base + i;
        if (idx < NN) s += g_deg[idx];
    }
    sums[t] = s;
    __syncthreads();
    for (int off = 1; off < 1024; off <<= 1) {
        int v = sums[t];
        if (t >= off) v += sums[t - off];
        __syncthreads();
        sums[t] = v;
        __syncthreads();
    }
    int run = sums[t] - s;  // exclusive base for this chunk
    for (int i = 0; i < C; i++) {
        int idx = base + i;
        if (idx < NN) {
            g_rowptr[idx] = run;
            g_cursor[idx] = run;
            run += g_deg[idx];
        }
    }
    if (t == 1023) g_rowptr[NN] = sums[1023];
}

// Grid-wide rsqrt (148 SMs' worth of MUFU, ~5us)
__global__ void k_dinv() {
    int i = blockIdx.x * 256 + threadIdx.x;
    if (i < NN) g_dinv[i] = rsqrtf((float)(g_deg[i] + 1));  // +1 self-loop
}

__global__ void k_fill(const int* __restrict__ row, const int* __restrict__ col) {
    int e = blockIdx.x * 256 + threadIdx.x;
    if (e < NE) {
        int r = row[e], c = col[e];
        int pos = atomicAdd(&g_cursor[c], 1);
        g_src[pos] = r;
        g_w[pos]   = g_dinv[r];
    }
}

// ---------------- bf16 helpers ----------------
__device__ __forceinline__ void bf16_split(float a, __nv_bfloat16& hi, __nv_bfloat16& lo) {
    hi = __float2bfloat16(a);
    lo = __float2bfloat16(a - __bfloat162float(hi));
}

__device__ __forceinline__ void unpack8(uint4 u, float f[8]) {
    float2 t;
    t = __bfloat1622float2(*reinterpret_cast<__nv_bfloat162*>(&u.x)); f[0] = t.x; f[1] = t.y;
    t = __bfloat1622float2(*reinterpret_cast<__nv_bfloat162*>(&u.y)); f[2] = t.x; f[3] = t.y;
    t = __bfloat1622float2(*reinterpret_cast<__nv_bfloat162*>(&u.z)); f[4] = t.x; f[5] = t.y;
    t = __bfloat1622float2(*reinterpret_cast<__nv_bfloat162*>(&u.w)); f[6] = t.x; f[7] = t.y;
}

__device__ __forceinline__ uint4 pack8(const float f[8]) {
    uint4 u;
    *reinterpret_cast<__nv_bfloat162*>(&u.x) = __floats2bfloat162_rn(f[0], f[1]);
    *reinterpret_cast<__nv_bfloat162*>(&u.y) = __floats2bfloat162_rn(f[2], f[3]);
    *reinterpret_cast<__nv_bfloat162*>(&u.z) = __floats2bfloat162_rn(f[4], f[5]);
    *reinterpret_cast<__nv_bfloat162*>(&u.w) = __floats2bfloat162_rn(f[6], f[7]);
    return u;
}

// W (fp32) -> bf16 hi/lo split (one-time per call; input-deterministic)
__global__ void k_splitW(const float* __restrict__ W, __nv_bfloat16* __restrict__ Wh,
                         __nv_bfloat16* __restrict__ Wl, int n) {
    int i = blockIdx.x * 256 + threadIdx.x;
    if (i < n) {
        __nv_bfloat16 h, l;
        bf16_split(W[i], h, l);
        Wh[i] = h; Wl[i] = l;
    }
}

// ---------------- aggregation, layer 1: fp32 x -> bf16 a1 (D=128) ----------
// out[c] = dinv[c] * ( sum_{src->c} dinv[src]*h[src] + dinv[c]*h[c] )
// Warp per node; thread d owns 4 features (float4).
__launch_bounds__(32)
__global__ void k_agg1(const float4* __restrict__ x4, __nv_bfloat162* __restrict__ out2) {
    __shared__ int   ssrc[32];
    __shared__ float sw[32];
    int c = blockIdx.x, d = threadIdx.x;
    int beg = g_rowptr[c], end = g_rowptr[c + 1];
    float dc = g_dinv[c];
    float4 self = x4[(size_t)c * 32 + d];
    float a0 = self.x * dc, a1 = self.y * dc, a2 = self.z * dc, a3 = self.w * dc;
    float b0 = 0.f, b1 = 0.f, b2 = 0.f, b3 = 0.f;
    for (int b = beg; b < end; b += 32) {
        int n = min(32, end - b);
        __syncwarp();
        if (d < n) { ssrc[d] = g_src[b + d]; sw[d] = g_w[b + d]; }
        __syncwarp();
        int i = 0;
        for (; i + 2 <= n; i += 2) {
            float4 v0 = x4[(size_t)ssrc[i + 0] * 32 + d];
            float4 v1 = x4[(size_t)ssrc[i + 1] * 32 + d];
            float w0 = sw[i + 0], w1 = sw[i + 1];
            a0 = fmaf(v0.x, w0, a0); a1 = fmaf(v0.y, w0, a1);
            a2 = fmaf(v0.z, w0, a2); a3 = fmaf(v0.w, w0, a3);
            b0 = fmaf(v1.x, w1, b0); b1 = fmaf(v1.y, w1, b1);
            b2 = fmaf(v1.z, w1, b2); b3 = fmaf(v1.w, w1, b3);
        }
        if (i < n) {
            float4 v0 = x4[(size_t)ssrc[i] * 32 + d];
            float w0 = sw[i];
            a0 = fmaf(v0.x, w0, a0); a1 = fmaf(v0.y, w0, a1);
            a2 = fmaf(v0.z, w0, a2); a3 = fmaf(v0.w, w0, a3);
        }
    }
    float r0 = (a0 + b0) * dc, r1 = (a1 + b1) * dc;
    float r2 = (a2 + b2) * dc, r3 = (a3 + b3) * dc;
    out2[(size_t)c * 64 + 2 * d + 0] = __floats2bfloat162_rn(r0, r1);
    out2[(size_t)c * 64 + 2 * d + 1] = __floats2bfloat162_rn(r2, r3);
}

// ---------------- aggregation, layer 2: bf16 h1 -> bf16 a2 (D=256) ---------
// Warp per node; thread d owns 8 features (uint4 = 8 bf16).
__launch_bounds__(32)
__global__ void k_agg2(const uint4* __restrict__ h, uint4* __restrict__ out) {
    __shared__ int   ssrc[32];
    __shared__ float sw[32];
    int c = blockIdx.x, d = threadIdx.x;
    int beg = g_rowptr[c], end = g_rowptr[c + 1];
    float dc = g_dinv[c];
    float acc[8], f[8], g[8];
    unpack8(h[(size_t)c * 32 + d], f);
#pragma unroll
    for (int j = 0; j < 8; j++) acc[j] = f[j] * dc;
    for (int b = beg; b < end; b += 32) {
        int n = min(32, end - b);
        __syncwarp();
        if (d < n) { ssrc[d] = g_src[b + d]; sw[d] = g_w[b + d]; }
        __syncwarp();
        int i = 0;
        for (; i + 2 <= n; i += 2) {
            uint4 u0 = h[(size_t)ssrc[i + 0] * 32 + d];
            uint4 u1 = h[(size_t)ssrc[i + 1] * 32 + d];
            float w0 = sw[i + 0], w1 = sw[i + 1];
            unpack8(u0, f); unpack8(u1, g);
#pragma unroll
            for (int j = 0; j < 8; j++) acc[j] = fmaf(f[j], w0, acc[j]);
#pragma unroll
            for (int j = 0; j < 8; j++) acc[j] = fmaf(g[j], w1, acc[j]);
        }
        if (i < n) {
            uint4 u0 = h[(size_t)ssrc[i] * 32 + d];
            float w0 = sw[i];
            unpack8(u0, f);
#pragma unroll
            for (int j = 0; j < 8; j++) acc[j] = fmaf(f[j], w0, acc[j]);
        }
    }
#pragma unroll
    for (int j = 0; j < 8; j++) acc[j] *= dc;
    out[(size_t)c * 32 + d] = pack8(acc);
}

// ---------------- tensor-core GEMM + bias + ReLU ----------------
// C[M,256] = relu(A[M,K](bf16) @ (Wh+Wl)[K,256](bf16 presplit) + b) -> bf16
// BM=128, BN=256 (full width, A staged once), BK=32, 512 threads (16 warps,
// each 32x64 = 2x4 m16n16k16 fragments, 2 MMAs per fragment: A*Bh + A*Bl).
template <int K>
__launch_bounds__(512)
__global__ void k_gemm_tc(const __nv_bfloat16* __restrict__ A,
                          const __nv_bfloat16* __restrict__ Wh,
                          const __nv_bfloat16* __restrict__ Wl,
                          const float* __restrict__ bias, __nv_bfloat16* __restrict__ Cout) {
    // union-aliased smem: tiles (44032 B) vs epilogue scratch (16 KB)
    __shared__ __align__(16) unsigned char smraw[10240 + 16896 + 16896];
    __nv_bfloat16 (*As)[40]  = (__nv_bfloat16(*)[40])(smraw);                 // [128][40]
    __nv_bfloat16 (*Bh)[264] = (__nv_bfloat16(*)[264])(smraw + 10240);        // [32][264]
    __nv_bfloat16 (*Bl)[264] = (__nv_bfloat16(*)[264])(smraw + 10240 + 16896);// [32][264]
    float* scr = (float*)smraw;                                               // [16][256]

    int tid = threadIdx.x, wid = tid >> 5, lane = tid & 31;
    int m0 = blockIdx.x * 128;
    int wm = wid >> 2, wn = wid & 3;  // warp tile: rows wm*32, cols wn*64

    wmma::fragment<wmma::accumulator, 16, 16, 16, float> acc[2][4];
#pragma unroll
    for (int mi = 0; mi < 2; mi++)
#pragma unroll
        for (int ni = 0; ni < 4; ni++) wmma::fill_fragment(acc[mi][ni], 0.0f);

    for (int k0 = 0; k0 < K; k0 += 32) {
        // A tile: 128x32 bf16 (one uint4 = 8 bf16 per thread)
        {
            int r = tid >> 2, c8 = (tid & 3) * 8;
            int gr = m0 + r;
            uint4 v = make_uint4(0u, 0u, 0u, 0u);
            if (gr < NN) v = *(const uint4*)&A[(size_t)gr * K + k0 + c8];
            *(uint4*)&As[r][c8] = v;
        }
        // B tiles: 32x256 bf16 x2, raw uint4 copies (2 per thread per matrix)
#pragma unroll
        for (int it = 0; it < 2; it++) {
            int p = tid + it * 512;
            int r = p >> 5, c8 = (p & 31) * 8;
            *(uint4*)&Bh[r][c8] = *(const uint4*)&Wh[(size_t)(k0 + r) * DH + c8];
            *(uint4*)&Bl[r][c8] = *(const uint4*)&Wl[(size_t)(k0 + r) * DH + c8];
        }
        __syncthreads();

#pragma unroll
        for (int ks = 0; ks < 2; ks++) {
            wmma::fragment<wmma::matrix_a, 16, 16, 16, __nv_bfloat16, wmma::row_major> ah[2];
#pragma unroll
            for (int mi = 0; mi < 2; mi++)
                wmma::load_matrix_sync(ah[mi], &As[wm * 32 + mi * 16][ks * 16], 40);
#pragma unroll
            for (int ni = 0; ni < 4; ni++) {
                wmma::fragment<wmma::matrix_b, 16, 16, 16, __nv_bfloat16, wmma::row_major> bh, bl;
                wmma::load_matrix_sync(bh, &Bh[ks * 16][wn * 64 + ni * 16], 264);
                wmma::load_matrix_sync(bl, &Bl[ks * 16][wn * 64 + ni * 16], 264);
#pragma unroll
                for (int mi = 0; mi < 2; mi++) {
                    wmma::mma_sync(acc[mi][ni], ah[mi], bh, acc[mi][ni]);
                    wmma::mma_sync(acc[mi][ni], ah[mi], bl, acc[mi][ni]);
                }
            }
        }
        __syncthreads();
    }

    // Epilogue: stage 16x16 fragments through per-warp smem, bias+relu, bf16 store.
    float* myscr = scr + wid * 256;
    int er = lane >> 1, ec = (lane & 1) * 8;
#pragma unroll
    for (int mi = 0; mi < 2; mi++) {
#pragma unroll
        for (int ni = 0; ni < 4; ni++) {
            wmma::store_matrix_sync(myscr, acc[mi][ni], 16, wmma::mem_row_major);
            __syncwarp();
            int gm = m0 + wm * 32 + mi * 16 + er;
            int gn = wn * 64 + ni * 16 + ec;
            if (gm < NN) {
                float4 b0 = *(const float4*)&bias[gn + 0];
                float4 b1 = *(const float4*)&bias[gn + 4];
                const float* s = &myscr[er * 16 + ec];
                float o[8];
                o[0] = fmaxf(s[0] + b0.x, 0.f); o[1] = fmaxf(s[1] + b0.y, 0.f);
                o[2] = fmaxf(s[2] + b0.z, 0.f); o[3] = fmaxf(s[3] + b0.w, 0.f);
                o[4] = fmaxf(s[4] + b1.x, 0.f); o[5] = fmaxf(s[5] + b1.y, 0.f);
                o[6] = fmaxf(s[6] + b1.z, 0.f); o[7] = fmaxf(s[7] + b1.w, 0.f);
                *(uint4*)&Cout[(size_t)gm * DH + gn] = pack8(o);
            }
            __syncwarp();
        }
    }
}

// ---------------- pooling (two-stage, bf16 input) ----------------
__global__ void k_bounds(const int* __restrict__ batch) {
    int g = threadIdx.x;
    if (g <= NG) {
        int lo = 0, hi = NN;
        while (lo < hi) {
            int mid = (lo + hi) >> 1;
            if (batch[mid] < g) lo = mid + 1; else hi = mid;
        }
        g_gstart[g] = lo;
    }
}

__launch_bounds__(128)
__global__ void k_pool1(const __nv_bfloat162* __restrict__ h2) {
    int g = blockIdx.x >> 4, chunk = blockIdx.x & (PCH - 1);
    int d = threadIdx.x;  // owns features 2d, 2d+1
    int beg = g_gstart[g], end = g_gstart[g + 1];
    long len = end - beg;
    int c0 = beg + (int)(len * chunk / PCH);
    int c1 = beg + (int)(len * (chunk + 1) / PCH);
    float sx0 = 0.f, sy0 = 0.f, sx1 = 0.f, sy1 = 0.f;
    int i = c0;
    for (; i + 2 <= c1; i += 2) {
        float2 f0 = __bfloat1622float2(h2[(size_t)(i + 0) * 128 + d]);
        float2 f1 = __bfloat1622float2(h2[(size_t)(i + 1) * 128 + d]);
        sx0 += f0.x; sy0 += f0.y;
        sx1 += f1.x; sy1 += f1.y;
    }
    if (i < c1) {
        float2 f0 = __bfloat1622float2(h2[(size_t)i * 128 + d]);
        sx0 += f0.x; sy0 += f0.y;
    }
    g_pp[(size_t)blockIdx.x * DH + 2 * d + 0] = sx0 + sx1;
    g_pp[(size_t)blockIdx.x * DH + 2 * d + 1] = sy0 + sy1;
}

__launch_bounds__(256)
__global__ void k_pool2(float* __restrict__ out) {
    int g = blockIdx.x, d = threadIdx.x;
    float s = 0.f;
#pragma unroll
    for (int c = 0; c < PCH; c++) s += g_pp[(size_t)(g * PCH + c) * DH + d];
    int cnt = g_gstart[g + 1] - g_gstart[g];
    out[g * DH + d] = s / fmaxf((float)cnt, 1.f);
}

// ---------------- launch ----------------
extern "C" void kernel_launch(void* const* d_in, const int* in_sizes, int n_in,
                              void* d_out, int out_size) {
    const float* x     = (const float*)d_in[0];
    const int*   ei    = (const int*)d_in[1];
    const int*   batch = (const int*)d_in[2];
    const float* W1    = (const float*)d_in[3];
    const float* b1    = (const float*)d_in[4];
    const float* W2    = (const float*)d_in[5];
    const float* b2    = (const float*)d_in[6];
    float*       out   = (float*)d_out;

    const int* row = ei;       // edge_index[0] = source
    const int* col = ei + NE;  // edge_index[1] = target

    __nv_bfloat16 *hA, *hB, *W1h, *W1l, *W2h, *W2l;
    cudaGetSymbolAddress((void**)&hA,  g_hA);
    cudaGetSymbolAddress((void**)&hB,  g_hB);
    cudaGetSymbolAddress((void**)&W1h, g_W1h);
    cudaGetSymbolAddress((void**)&W1l, g_W1l);
    cudaGetSymbolAddress((void**)&W2h, g_W2h);
    cudaGetSymbolAddress((void**)&W2l, g_W2l);

    int nb_nodes = (NN + 255) / 256;
    int nb_edges = (NE + 255) / 256;

    // CSR build + W presplit (fully re-run every call: graph-replay safe)
    k_zero_deg<<<nb_nodes, 256>>>();
    k_count<<<nb_edges, 256>>>(col);
    k_scan<<<1, 1024>>>();
    k_dinv<<<nb_nodes, 256>>>();
    k_fill<<<nb_edges, 256>>>(row, col);
    k_bounds<<<1, 128>>>(batch);
    k_splitW<<<(DIN * DH + 255) / 256, 256>>>(W1, W1h, W1l, DIN * DH);
    k_splitW<<<(DH * DH + 255) / 256, 256>>>(W2, W2h, W2l, DH * DH);

    int gm = (NN + 127) / 128;  // 782
    // Layer 1: agg(x) [D=128] -> @W1 + b1, relu (agg commutes with linear)
    k_agg1<<<NN, 32>>>((const float4*)x, (__nv_bfloat162*)hA);
    k_gemm_tc<DIN><<<gm, 512>>>(hA, W1h, W1l, b1, hB);
    // Layer 2: agg(h1) [D=256] -> @W2 + b2, relu
    k_agg2<<<NN, 32>>>((const uint4*)hB, (uint4*)hA);
    k_gemm_tc<DH><<<gm, 512>>>(hA, W2h, W2l, b2, hB);
    // Global mean pool (two-stage)
    k_pool1<<<NG * PCH, 128>>>((const __nv_bfloat162*)hB);
    k_pool2<<<NG, 256>>>(out);
}

// round 15
// speedup vs baseline: 1.5341x; 1.5341x over previous
#include <cuda_runtime.h>
#include <cuda_bf16.h>
#include <cuda_pipeline.h>
#include <mma.h>

using namespace nvcuda;

// Problem constants (fixed shapes per reference)
#define NN  100000
#define NE  1600000
#define NG  64
#define DIN 128
#define DH  256
#define PCH 16   // pool chunks per graph

// ---------------- scratch (device globals; no allocation anywhere) ----------
__device__ __align__(16) __nv_bfloat16 g_hA[(size_t)NN * DH];  // 51.2 MB
__device__ __align__(16) __nv_bfloat16 g_hB[(size_t)NN * DH];  // 51.2 MB
__device__ __align__(16) __nv_bfloat16 g_W1h[DIN * DH], g_W1l[DIN * DH];  // 64 KB each
__device__ __align__(16) __nv_bfloat16 g_W2h[DH * DH],  g_W2l[DH * DH];   // 128 KB each
__device__ float g_dinv[NN];
__device__ int   g_deg[NN];
__device__ int   g_rowptr[NN + 1];
__device__ int   g_cursor[NN];
__device__ int   g_src[NE];
__device__ float g_w[NE];
__device__ int   g_gstart[NG + 1];
__device__ float g_pp[NG * PCH * DH];       // pool partials (1 MB)

// ---------------- CSR build ----------------
__global__ void k_zero_deg() {
    int i = blockIdx.x * 256 + threadIdx.x;
    if (i < NN) g_deg[i] = 0;
}

__global__ void k_count(const int* __restrict__ col) {
    int e = blockIdx.x * 256 + threadIdx.x;
    if (e < NE) atomicAdd(&g_deg[col[e]], 1);
}

// Single-block exclusive scan over degrees -> rowptr, cursor. (int work ONLY:
// rsqrtf here serializes 100K MUFU ops onto one SM.)
__global__ void k_scan() {
    __shared__ int sums[1024];
    int t = threadIdx.x;
    const int C = (NN + 1023) / 1024;  // 98
    int base = t * C, s = 0;
    for (int i = 0; i < C; i++) {
        int idx = base + i;
        if (idx < NN) s += g_deg[idx];
    }
    sums[t] = s;
    __syncthreads();
    for (int off = 1; off < 1024; off <<= 1) {
        int v = sums[t];
        if (t >= off) v += sums[t - off];
        __syncthreads();
        sums[t] = v;
        __syncthreads();
    }
    int run = sums[t] - s;  // exclusive base for this chunk
    for (int i = 0; i < C; i++) {
        int idx = base + i;
        if (idx < NN) {
            g_rowptr[idx] = run;
            g_cursor[idx] = run;
            run += g_deg[idx];
        }
    }
    if (t == 1023) g_rowptr[NN] = sums[1023];
}

// Grid-wide rsqrt (148 SMs' worth of MUFU)
__global__ void k_dinv() {
    int i = blockIdx.x * 256 + threadIdx.x;
    if (i < NN) g_dinv[i] = rsqrtf((float)(g_deg[i] + 1));  // +1 self-loop
}

__global__ void k_fill(const int* __restrict__ row, const int* __restrict__ col) {
    int e = blockIdx.x * 256 + threadIdx.x;
    if (e < NE) {
        int r = row[e], c = col[e];
        int pos = atomicAdd(&g_cursor[c], 1);
        g_src[pos] = r;
        g_w[pos]   = g_dinv[r];
    }
}

// ---------------- bf16 helpers ----------------
__device__ __forceinline__ void bf16_split(float a, __nv_bfloat16& hi, __nv_bfloat16& lo) {
    hi = __float2bfloat16(a);
    lo = __float2bfloat16(a - __bfloat162float(hi));
}

__device__ __forceinline__ void unpack8(uint4 u, float f[8]) {
    float2 t;
    t = __bfloat1622float2(*reinterpret_cast<__nv_bfloat162*>(&u.x)); f[0] = t.x; f[1] = t.y;
    t = __bfloat1622float2(*reinterpret_cast<__nv_bfloat162*>(&u.y)); f[2] = t.x; f[3] = t.y;
    t = __bfloat1622float2(*reinterpret_cast<__nv_bfloat162*>(&u.z)); f[4] = t.x; f[5] = t.y;
    t = __bfloat1622float2(*reinterpret_cast<__nv_bfloat162*>(&u.w)); f[6] = t.x; f[7] = t.y;
}

__device__ __forceinline__ uint4 pack8(const float f[8]) {
    uint4 u;
    *reinterpret_cast<__nv_bfloat162*>(&u.x) = __floats2bfloat162_rn(f[0], f[1]);
    *reinterpret_cast<__nv_bfloat162*>(&u.y) = __floats2bfloat162_rn(f[2], f[3]);
    *reinterpret_cast<__nv_bfloat162*>(&u.z) = __floats2bfloat162_rn(f[4], f[5]);
    *reinterpret_cast<__nv_bfloat162*>(&u.w) = __floats2bfloat162_rn(f[6], f[7]);
    return u;
}

// W (fp32) -> bf16 hi/lo split (one-time per call; input-deterministic)
__global__ void k_splitW(const float* __restrict__ W, __nv_bfloat16* __restrict__ Wh,
                         __nv_bfloat16* __restrict__ Wl, int n) {
    int i = blockIdx.x * 256 + threadIdx.x;
    if (i < n) {
        __nv_bfloat16 h, l;
        bf16_split(W[i], h, l);
        Wh[i] = h; Wl[i] = l;
    }
}

// ---------------- aggregation, layer 1: fp32 x -> bf16 a1 (D=128) ----------
// out[c] = dinv[c] * ( sum_{src->c} dinv[src]*h[src] + dinv[c]*h[c] )
// Warp per node; thread d owns 4 features (float4).
__launch_bounds__(32)
__global__ void k_agg1(const float4* __restrict__ x4, __nv_bfloat162* __restrict__ out2) {
    __shared__ int   ssrc[32];
    __shared__ float sw[32];
    int c = blockIdx.x, d = threadIdx.x;
    int beg = g_rowptr[c], end = g_rowptr[c + 1];
    float dc = g_dinv[c];
    float4 self = x4[(size_t)c * 32 + d];
    float a0 = self.x * dc, a1 = self.y * dc, a2 = self.z * dc, a3 = self.w * dc;
    float b0 = 0.f, b1 = 0.f, b2 = 0.f, b3 = 0.f;
    for (int b = beg; b < end; b += 32) {
        int n = min(32, end - b);
        __syncwarp();
        if (d < n) { ssrc[d] = g_src[b + d]; sw[d] = g_w[b + d]; }
        __syncwarp();
        int i = 0;
        for (; i + 2 <= n; i += 2) {
            float4 v0 = x4[(size_t)ssrc[i + 0] * 32 + d];
            float4 v1 = x4[(size_t)ssrc[i + 1] * 32 + d];
            float w0 = sw[i + 0], w1 = sw[i + 1];
            a0 = fmaf(v0.x, w0, a0); a1 = fmaf(v0.y, w0, a1);
            a2 = fmaf(v0.z, w0, a2); a3 = fmaf(v0.w, w0, a3);
            b0 = fmaf(v1.x, w1, b0); b1 = fmaf(v1.y, w1, b1);
            b2 = fmaf(v1.z, w1, b2); b3 = fmaf(v1.w, w1, b3);
        }
        if (i < n) {
            float4 v0 = x4[(size_t)ssrc[i] * 32 + d];
            float w0 = sw[i];
            a0 = fmaf(v0.x, w0, a0); a1 = fmaf(v0.y, w0, a1);
            a2 = fmaf(v0.z, w0, a2); a3 = fmaf(v0.w, w0, a3);
        }
    }
    float r0 = (a0 + b0) * dc, r1 = (a1 + b1) * dc;
    float r2 = (a2 + b2) * dc, r3 = (a3 + b3) * dc;
    out2[(size_t)c * 64 + 2 * d + 0] = __floats2bfloat162_rn(r0, r1);
    out2[(size_t)c * 64 + 2 * d + 1] = __floats2bfloat162_rn(r2, r3);
}

// ---------------- aggregation, layer 2: bf16 h1 -> bf16 a2 (D=256) ---------
// Warp per node; thread d owns 8 features (uint4 = 8 bf16).
__launch_bounds__(32)
__global__ void k_agg2(const uint4* __restrict__ h, uint4* __restrict__ out) {
    __shared__ int   ssrc[32];
    __shared__ float sw[32];
    int c = blockIdx.x, d = threadIdx.x;
    int beg = g_rowptr[c], end = g_rowptr[c + 1];
    float dc = g_dinv[c];
    float acc[8], f[8], g[8];
    unpack8(h[(size_t)c * 32 + d], f);
#pragma unroll
    for (int j = 0; j < 8; j++) acc[j] = f[j] * dc;
    for (int b = beg; b < end; b += 32) {
        int n = min(32, end - b);
        __syncwarp();
        if (d < n) { ssrc[d] = g_src[b + d]; sw[d] = g_w[b + d]; }
        __syncwarp();
        int i = 0;
        for (; i + 2 <= n; i += 2) {
            uint4 u0 = h[(size_t)ssrc[i + 0] * 32 + d];
            uint4 u1 = h[(size_t)ssrc[i + 1] * 32 + d];
            float w0 = sw[i + 0], w1 = sw[i + 1];
            unpack8(u0, f); unpack8(u1, g);
#pragma unroll
            for (int j = 0; j < 8; j++) acc[j] = fmaf(f[j], w0, acc[j]);
#pragma unroll
            for (int j = 0; j < 8; j++) acc[j] = fmaf(g[j], w1, acc[j]);
        }
        if (i < n) {
            uint4 u0 = h[(size_t)ssrc[i] * 32 + d];
            float w0 = sw[i];
            unpack8(u0, f);
#pragma unroll
            for (int j = 0; j < 8; j++) acc[j] = fmaf(f[j], w0, acc[j]);
        }
    }
#pragma unroll
    for (int j = 0; j < 8; j++) acc[j] *= dc;
    out[(size_t)c * 32 + d] = pack8(acc);
}

// ---------------- tensor-core GEMM + bias + ReLU (double-buffered) ---------
// C[M,256] = relu(A[M,K](bf16) @ (Wh+Wl)[K,256](bf16 presplit) + b) -> bf16
// BM=128, BN=256, BK=32, 512 threads (16 warps, each 32x64, 2 MMAs/fragment).
// cp.async double-buffering: tile t+1 loads overlap tile t MMAs.
#define TILE_BYTES (10240 + 16896 + 16896)

template <int K>
__launch_bounds__(512)
__global__ void k_gemm_tc(const __nv_bfloat16* __restrict__ A,
                          const __nv_bfloat16* __restrict__ Wh,
                          const __nv_bfloat16* __restrict__ Wl,
                          const float* __restrict__ bias, __nv_bfloat16* __restrict__ Cout) {
    constexpr int NT = K / 32;
    __shared__ __align__(16) unsigned char smraw[2][TILE_BYTES];
    float* scr = (float*)smraw[0];  // epilogue scratch aliases buffer 0

    int tid = threadIdx.x, wid = tid >> 5, lane = tid & 31;
    int m0 = blockIdx.x * 128;
    int wm = wid >> 2, wn = wid & 3;  // warp tile: rows wm*32, cols wn*64

    // per-thread load coordinates
    int ar = tid >> 2, ac8 = (tid & 3) * 8;  // A: 128 rows x 32 k, 16B each
    int gr = m0 + ar;

    wmma::fragment<wmma::accumulator, 16, 16, 16, float> acc[2][4];
#pragma unroll
    for (int mi = 0; mi < 2; mi++)
#pragma unroll
        for (int ni = 0; ni < 4; ni++) wmma::fill_fragment(acc[mi][ni], 0.0f);

    // ---- prefetch tile 0 into buffer 0 ----
    {
        __nv_bfloat16 (*As)[40]  = (__nv_bfloat16(*)[40])(smraw[0]);
        __nv_bfloat16 (*Bh)[264] = (__nv_bfloat16(*)[264])(smraw[0] + 10240);
        __nv_bfloat16 (*Bl)[264] = (__nv_bfloat16(*)[264])(smraw[0] + 10240 + 16896);
        if (gr < NN)
            __pipeline_memcpy_async(&As[ar][ac8], &A[(size_t)gr * K + ac8], 16);
        else
            *(uint4*)&As[ar][ac8] = make_uint4(0u, 0u, 0u, 0u);
#pragma unroll
        for (int it = 0; it < 2; it++) {
            int p = tid + it * 512;
            int r = p >> 5, c8 = (p & 31) * 8;
            __pipeline_memcpy_async(&Bh[r][c8], &Wh[(size_t)r * DH + c8], 16);
            __pipeline_memcpy_async(&Bl[r][c8], &Wl[(size_t)r * DH + c8], 16);
        }
        __pipeline_commit();
    }

    for (int t = 0; t < NT; t++) {
        // ---- prefetch tile t+1 into the other buffer, then wait for tile t ----
        if (t + 1 < NT) {
            int k0 = (t + 1) * 32;
            int nb = (t + 1) & 1;
            __nv_bfloat16 (*As)[40]  = (__nv_bfloat16(*)[40])(smraw[nb]);
            __nv_bfloat16 (*Bh)[264] = (__nv_bfloat16(*)[264])(smraw[nb] + 10240);
            __nv_bfloat16 (*Bl)[264] = (__nv_bfloat16(*)[264])(smraw[nb] + 10240 + 16896);
            if (gr < NN)
                __pipeline_memcpy_async(&As[ar][ac8], &A[(size_t)gr * K + k0 + ac8], 16);
            else
                *(uint4*)&As[ar][ac8] = make_uint4(0u, 0u, 0u, 0u);
#pragma unroll
            for (int it = 0; it < 2; it++) {
                int p = tid + it * 512;
                int r = p >> 5, c8 = (p & 31) * 8;
                __pipeline_memcpy_async(&Bh[r][c8], &Wh[(size_t)(k0 + r) * DH + c8], 16);
                __pipeline_memcpy_async(&Bl[r][c8], &Wl[(size_t)(k0 + r) * DH + c8], 16);
            }
            __pipeline_commit();
            __pipeline_wait_prior(1);   // tile t complete; t+1 may be in flight
        } else {
            __pipeline_wait_prior(0);
        }
        __syncthreads();

        // ---- compute on buffer t&1 ----
        {
            int cb = t & 1;
            __nv_bfloat16 (*As)[40]  = (__nv_bfloat16(*)[40])(smraw[cb]);
            __nv_bfloat16 (*Bh)[264] = (__nv_bfloat16(*)[264])(smraw[cb] + 10240);
            __nv_bfloat16 (*Bl)[264] = (__nv_bfloat16(*)[264])(smraw[cb] + 10240 + 16896);
#pragma unroll
            for (int ks = 0; ks < 2; ks++) {
                wmma::fragment<wmma::matrix_a, 16, 16, 16, __nv_bfloat16, wmma::row_major> ah[2];
#pragma unroll
                for (int mi = 0; mi < 2; mi++)
                    wmma::load_matrix_sync(ah[mi], &As[wm * 32 + mi * 16][ks * 16], 40);
#pragma unroll
                for (int ni = 0; ni < 4; ni++) {
                    wmma::fragment<wmma::matrix_b, 16, 16, 16, __nv_bfloat16, wmma::row_major> bh, bl;
                    wmma::load_matrix_sync(bh, &Bh[ks * 16][wn * 64 + ni * 16], 264);
                    wmma::load_matrix_sync(bl, &Bl[ks * 16][wn * 64 + ni * 16], 264);
#pragma unroll
                    for (int mi = 0; mi < 2; mi++) {
                        wmma::mma_sync(acc[mi][ni], ah[mi], bh, acc[mi][ni]);
                        wmma::mma_sync(acc[mi][ni], ah[mi], bl, acc[mi][ni]);
                    }
                }
            }
        }
        __syncthreads();  // all warps done with buffer t&1 before it's refilled
    }

    // Epilogue: stage 16x16 fragments through per-warp smem, bias+relu, bf16 store.
    float* myscr = scr + wid * 256;
    int er = lane >> 1, ec = (lane & 1) * 8;
#pragma unroll
    for (int mi = 0; mi < 2; mi++) {
#pragma unroll
        for (int ni = 0; ni < 4; ni++) {
            wmma::store_matrix_sync(myscr, acc[mi][ni], 16, wmma::mem_row_major);
            __syncwarp();
            int gm = m0 + wm * 32 + mi * 16 + er;
            int gn = wn * 64 + ni * 16 + ec;
            if (gm < NN) {
                float4 b0 = *(const float4*)&bias[gn + 0];
                float4 b1 = *(const float4*)&bias[gn + 4];
                const float* s = &myscr[er * 16 + ec];
                float o[8];
                o[0] = fmaxf(s[0] + b0.x, 0.f); o[1] = fmaxf(s[1] + b0.y, 0.f);
                o[2] = fmaxf(s[2] + b0.z, 0.f); o[3] = fmaxf(s[3] + b0.w, 0.f);
                o[4] = fmaxf(s[4] + b1.x, 0.f); o[5] = fmaxf(s[5] + b1.y, 0.f);
                o[6] = fmaxf(s[6] + b1.z, 0.f); o[7] = fmaxf(s[7] + b1.w, 0.f);
                *(uint4*)&Cout[(size_t)gm * DH + gn] = pack8(o);
            }
            __syncwarp();
        }
    }
}

// ---------------- pooling (two-stage, bf16 input) ----------------
__global__ void k_bounds(const int* __restrict__ batch) {
    int g = threadIdx.x;
    if (g <= NG) {
        int lo = 0, hi = NN;
        while (lo < hi) {
            int mid = (lo + hi) >> 1;
            if (batch[mid] < g) lo = mid + 1; else hi = mid;
        }
        g_gstart[g] = lo;
    }
}

__launch_bounds__(128)
__global__ void k_pool1(const __nv_bfloat162* __restrict__ h2) {
    int g = blockIdx.x >> 4, chunk = blockIdx.x & (PCH - 1);
    int d = threadIdx.x;  // owns features 2d, 2d+1
    int beg = g_gstart[g], end = g_gstart[g + 1];
    long len = end - beg;
    int c0 = beg + (int)(len * chunk / PCH);
    int c1 = beg + (int)(len * (chunk + 1) / PCH);
    float sx0 = 0.f, sy0 = 0.f, sx1 = 0.f, sy1 = 0.f;
    int i = c0;
    for (; i + 2 <= c1; i += 2) {
        float2 f0 = __bfloat1622float2(h2[(size_t)(i + 0) * 128 + d]);
        float2 f1 = __bfloat1622float2(h2[(size_t)(i + 1) * 128 + d]);
        sx0 += f0.x; sy0 += f0.y;
        sx1 += f1.x; sy1 += f1.y;
    }
    if (i < c1) {
        float2 f0 = __bfloat1622float2(h2[(size_t)i * 128 + d]);
        sx0 += f0.x; sy0 += f0.y;
    }
    g_pp[(size_t)blockIdx.x * DH + 2 * d + 0] = sx0 + sx1;
    g_pp[(size_t)blockIdx.x * DH + 2 * d + 1] = sy0 + sy1;
}

__launch_bounds__(256)
__global__ void k_pool2(float* __restrict__ out) {
    int g = blockIdx.x, d = threadIdx.x;
    float s = 0.f;
#pragma unroll
    for (int c = 0; c < PCH; c++) s += g_pp[(size_t)(g * PCH + c) * DH + d];
    int cnt = g_gstart[g + 1] - g_gstart[g];
    out[g * DH + d] = s / fmaxf((float)cnt, 1.f);
}

// ---------------- launch ----------------
extern "C" void kernel_launch(void* const* d_in, const int* in_sizes, int n_in,
                              void* d_out, int out_size) {
    const float* x     = (const float*)d_in[0];
    const int*   ei    = (const int*)d_in[1];
    const int*   batch = (const int*)d_in[2];
    const float* W1    = (const float*)d_in[3];
    const float* b1    = (const float*)d_in[4];
    const float* W2    = (const float*)d_in[5];
    const float* b2    = (const float*)d_in[6];
    float*       out   = (float*)d_out;

    const int* row = ei;       // edge_index[0] = source
    const int* col = ei + NE;  // edge_index[1] = target

    __nv_bfloat16 *hA, *hB, *W1h, *W1l, *W2h, *W2l;
    cudaGetSymbolAddress((void**)&hA,  g_hA);
    cudaGetSymbolAddress((void**)&hB,  g_hB);
    cudaGetSymbolAddress((void**)&W1h, g_W1h);
    cudaGetSymbolAddress((void**)&W1l, g_W1l);
    cudaGetSymbolAddress((void**)&W2h, g_W2h);
    cudaGetSymbolAddress((void**)&W2l, g_W2l);

    int nb_nodes = (NN + 255) / 256;
    int nb_edges = (NE + 255) / 256;

    // CSR build + W presplit (fully re-run every call: graph-replay safe)
    k_zero_deg<<<nb_nodes, 256>>>();
    k_count<<<nb_edges, 256>>>(col);
    k_scan<<<1, 1024>>>();
    k_dinv<<<nb_nodes, 256>>>();
    k_fill<<<nb_edges, 256>>>(row, col);
    k_bounds<<<1, 128>>>(batch);
    k_splitW<<<(DIN * DH + 255) / 256, 256>>>(W1, W1h, W1l, DIN * DH);
    k_splitW<<<(DH * DH + 255) / 256, 256>>>(W2, W2h, W2l, DH * DH);

    int gm = (NN + 127) / 128;  // 782
    // Layer 1: agg(x) [D=128] -> @W1 + b1, relu (agg commutes with linear)
    k_agg1<<<NN, 32>>>((const float4*)x, (__nv_bfloat162*)hA);
    k_gemm_tc<DIN><<<gm, 512>>>(hA, W1h, W1l, b1, hB);
    // Layer 2: agg(h1) [D=256] -> @W2 + b2, relu
    k_agg2<<<NN, 32>>>((const uint4*)hB, (uint4*)hA);
    k_gemm_tc<DH><<<gm, 512>>>(hA, W2h, W2l, b2, hB);
    // Global mean pool (two-stage)
    k_pool1<<<NG * PCH, 128>>>((const __nv_bfloat162*)hB);
    k_pool2<<<NG, 256>>>(out);
}

// round 16
// speedup vs baseline: 1.5555x; 1.0140x over previous
#include <cuda_runtime.h>
#include <cuda_bf16.h>
#include <cuda_pipeline.h>
#include <mma.h>

using namespace nvcuda;

// Problem constants (fixed shapes per reference)
#define NN  100000
#define NE  1600000
#define NG  64
#define DIN 128
#define DH  256
#define PCH 16   // pool chunks per graph

// ---------------- scratch (device globals; no allocation anywhere) ----------
__device__ __align__(16) __nv_bfloat16 g_hA[(size_t)NN * DH];  // 51.2 MB
__device__ __align__(16) __nv_bfloat16 g_hB[(size_t)NN * DH];  // 51.2 MB
__device__ __align__(16) __nv_bfloat16 g_x16[(size_t)NN * DIN]; // 25.6 MB bf16 x
__device__ __align__(16) __nv_bfloat16 g_W1h[DIN * DH], g_W1l[DIN * DH];  // 64 KB each
__device__ __align__(16) __nv_bfloat16 g_W2h[DH * DH],  g_W2l[DH * DH];   // 128 KB each
__device__ float g_dinv[NN];
__device__ int   g_deg[NN];
__device__ int   g_rowptr[NN + 1];
__device__ int   g_cursor[NN];
__device__ int   g_src[NE];
__device__ float g_w[NE];
__device__ int   g_gstart[NG + 1];
__device__ float g_pp[NG * PCH * DH];       // pool partials (1 MB)

// ---------------- CSR build ----------------
__global__ void k_zero_deg() {
    int i = blockIdx.x * 256 + threadIdx.x;
    if (i < NN) g_deg[i] = 0;
}

__global__ void k_count(const int* __restrict__ col) {
    int e = blockIdx.x * 256 + threadIdx.x;
    if (e < NE) atomicAdd(&g_deg[col[e]], 1);
}

// Single-block exclusive scan over degrees -> rowptr, cursor. (int work ONLY:
// rsqrtf here serializes 100K MUFU ops onto one SM.)
__global__ void k_scan() {
    __shared__ int sums[1024];
    int t = threadIdx.x;
    const int C = (NN + 1023) / 1024;  // 98
    int base = t * C, s = 0;
    for (int i = 0; i < C; i++) {
        int idx = base + i;
        if (idx < NN) s += g_deg[idx];
    }
    sums[t] = s;
    __syncthreads();
    for (int off = 1; off < 1024; off <<= 1) {
        int v = sums[t];
        if (t >= off) v += sums[t - off];
        __syncthreads();
        sums[t] = v;
        __syncthreads();
    }
    int run = sums[t] - s;  // exclusive base for this chunk
    for (int i = 0; i < C; i++) {
        int idx = base + i;
        if (idx < NN) {
            g_rowptr[idx] = run;
            g_cursor[idx] = run;
            run += g_deg[idx];
        }
    }
    if (t == 1023) g_rowptr[NN] = sums[1023];
}

// Grid-wide rsqrt (148 SMs' worth of MUFU)
__global__ void k_dinv() {
    int i = blockIdx.x * 256 + threadIdx.x;
    if (i < NN) g_dinv[i] = rsqrtf((float)(g_deg[i] + 1));  // +1 self-loop
}

__global__ void k_fill(const int* __restrict__ row, const int* __restrict__ col) {
    int e = blockIdx.x * 256 + threadIdx.x;
    if (e < NE) {
        int r = row[e], c = col[e];
        int pos = atomicAdd(&g_cursor[c], 1);
        g_src[pos] = r;
        g_w[pos]   = g_dinv[r];
    }
}

// ---------------- bf16 helpers ----------------
__device__ __forceinline__ void bf16_split(float a, __nv_bfloat16& hi, __nv_bfloat16& lo) {
    hi = __float2bfloat16(a);
    lo = __float2bfloat16(a - __bfloat162float(hi));
}

__device__ __forceinline__ void unpack4(uint2 u, float f[4]) {
    float2 t;
    t = __bfloat1622float2(*reinterpret_cast<__nv_bfloat162*>(&u.x)); f[0] = t.x; f[1] = t.y;
    t = __bfloat1622float2(*reinterpret_cast<__nv_bfloat162*>(&u.y)); f[2] = t.x; f[3] = t.y;
}

__device__ __forceinline__ void unpack8(uint4 u, float f[8]) {
    float2 t;
    t = __bfloat1622float2(*reinterpret_cast<__nv_bfloat162*>(&u.x)); f[0] = t.x; f[1] = t.y;
    t = __bfloat1622float2(*reinterpret_cast<__nv_bfloat162*>(&u.y)); f[2] = t.x; f[3] = t.y;
    t = __bfloat1622float2(*reinterpret_cast<__nv_bfloat162*>(&u.z)); f[4] = t.x; f[5] = t.y;
    t = __bfloat1622float2(*reinterpret_cast<__nv_bfloat162*>(&u.w)); f[6] = t.x; f[7] = t.y;
}

__device__ __forceinline__ uint4 pack8(const float f[8]) {
    uint4 u;
    *reinterpret_cast<__nv_bfloat162*>(&u.x) = __floats2bfloat162_rn(f[0], f[1]);
    *reinterpret_cast<__nv_bfloat162*>(&u.y) = __floats2bfloat162_rn(f[2], f[3]);
    *reinterpret_cast<__nv_bfloat162*>(&u.z) = __floats2bfloat162_rn(f[4], f[5]);
    *reinterpret_cast<__nv_bfloat162*>(&u.w) = __floats2bfloat162_rn(f[6], f[7]);
    return u;
}

// x (fp32) -> bf16 (one-time per call; input-deterministic)
__global__ void k_cvt_x(const float4* __restrict__ x4, uint2* __restrict__ o) {
    int i = blockIdx.x * 256 + threadIdx.x;
    if (i < NN * DIN / 4) {
        float4 v = x4[i];
        uint2 u;
        *reinterpret_cast<__nv_bfloat162*>(&u.x) = __floats2bfloat162_rn(v.x, v.y);
        *reinterpret_cast<__nv_bfloat162*>(&u.y) = __floats2bfloat162_rn(v.z, v.w);
        o[i] = u;
    }
}

// W (fp32) -> bf16 hi/lo split (one-time per call; input-deterministic)
__global__ void k_splitW(const float* __restrict__ W, __nv_bfloat16* __restrict__ Wh,
                         __nv_bfloat16* __restrict__ Wl, int n) {
    int i = blockIdx.x * 256 + threadIdx.x;
    if (i < n) {
        __nv_bfloat16 h, l;
        bf16_split(W[i], h, l);
        Wh[i] = h; Wl[i] = l;
    }
}

// ---------------- aggregation, layer 1: bf16 x -> bf16 a1 (D=128) ----------
// out[c] = dinv[c] * ( sum_{src->c} dinv[src]*h[src] + dinv[c]*h[c] )
// 4 nodes per 128-thread block, one warp each (64 warps/SM occupancy).
// Lane d owns 4 features (uint2 = 4 bf16).
__launch_bounds__(128)
__global__ void k_agg1(const uint2* __restrict__ x2, uint2* __restrict__ out2) {
    __shared__ int   ssrc[4][32];
    __shared__ float sw[4][32];
    int wg = threadIdx.x >> 5, d = threadIdx.x & 31;
    int c = blockIdx.x * 4 + wg;
    if (c >= NN) return;
    int beg = g_rowptr[c], end = g_rowptr[c + 1];
    float dc = g_dinv[c];
    float f[4], g[4];
    unpack4(x2[(size_t)c * 32 + d], f);
    float a0 = f[0] * dc, a1 = f[1] * dc, a2 = f[2] * dc, a3 = f[3] * dc;
    float b0 = 0.f, b1 = 0.f, b2 = 0.f, b3 = 0.f;
    for (int b = beg; b < end; b += 32) {
        int n = min(32, end - b);
        __syncwarp();
        if (d < n) { ssrc[wg][d] = g_src[b + d]; sw[wg][d] = g_w[b + d]; }
        __syncwarp();
        int i = 0;
        for (; i + 2 <= n; i += 2) {
            uint2 u0 = x2[(size_t)ssrc[wg][i + 0] * 32 + d];
            uint2 u1 = x2[(size_t)ssrc[wg][i + 1] * 32 + d];
            float w0 = sw[wg][i + 0], w1 = sw[wg][i + 1];
            unpack4(u0, f); unpack4(u1, g);
            a0 = fmaf(f[0], w0, a0); a1 = fmaf(f[1], w0, a1);
            a2 = fmaf(f[2], w0, a2); a3 = fmaf(f[3], w0, a3);
            b0 = fmaf(g[0], w1, b0); b1 = fmaf(g[1], w1, b1);
            b2 = fmaf(g[2], w1, b2); b3 = fmaf(g[3], w1, b3);
        }
        if (i < n) {
            uint2 u0 = x2[(size_t)ssrc[wg][i] * 32 + d];
            float w0 = sw[wg][i];
            unpack4(u0, f);
            a0 = fmaf(f[0], w0, a0); a1 = fmaf(f[1], w0, a1);
            a2 = fmaf(f[2], w0, a2); a3 = fmaf(f[3], w0, a3);
        }
    }
    float r0 = (a0 + b0) * dc, r1 = (a1 + b1) * dc;
    float r2 = (a2 + b2) * dc, r3 = (a3 + b3) * dc;
    uint2 u;
    *reinterpret_cast<__nv_bfloat162*>(&u.x) = __floats2bfloat162_rn(r0, r1);
    *reinterpret_cast<__nv_bfloat162*>(&u.y) = __floats2bfloat162_rn(r2, r3);
    out2[(size_t)c * 32 + d] = u;
}

// ---------------- aggregation, layer 2: bf16 h1 -> bf16 a2 (D=256) ---------
// 4 nodes per 128-thread block, one warp each. Lane d owns 8 features (uint4).
__launch_bounds__(128)
__global__ void k_agg2(const uint4* __restrict__ h, uint4* __restrict__ out) {
    __shared__ int   ssrc[4][32];
    __shared__ float sw[4][32];
    int wg = threadIdx.x >> 5, d = threadIdx.x & 31;
    int c = blockIdx.x * 4 + wg;
    if (c >= NN) return;
    int beg = g_rowptr[c], end = g_rowptr[c + 1];
    float dc = g_dinv[c];
    float acc[8], f[8], g[8];
    unpack8(h[(size_t)c * 32 + d], f);
#pragma unroll
    for (int j = 0; j < 8; j++) acc[j] = f[j] * dc;
    for (int b = beg; b < end; b += 32) {
        int n = min(32, end - b);
        __syncwarp();
        if (d < n) { ssrc[wg][d] = g_src[b + d]; sw[wg][d] = g_w[b + d]; }
        __syncwarp();
        int i = 0;
        for (; i + 2 <= n; i += 2) {
            uint4 u0 = h[(size_t)ssrc[wg][i + 0] * 32 + d];
            uint4 u1 = h[(size_t)ssrc[wg][i + 1] * 32 + d];
            float w0 = sw[wg][i + 0], w1 = sw[wg][i + 1];
            unpack8(u0, f); unpack8(u1, g);
#pragma unroll
            for (int j = 0; j < 8; j++) acc[j] = fmaf(f[j], w0, acc[j]);
#pragma unroll
            for (int j = 0; j < 8; j++) acc[j] = fmaf(g[j], w1, acc[j]);
        }
        if (i < n) {
            uint4 u0 = h[(size_t)ssrc[wg][i] * 32 + d];
            float w0 = sw[wg][i];
            unpack8(u0, f);
#pragma unroll
            for (int j = 0; j < 8; j++) acc[j] = fmaf(f[j], w0, acc[j]);
        }
    }
#pragma unroll
    for (int j = 0; j < 8; j++) acc[j] *= dc;
    out[(size_t)c * 32 + d] = pack8(acc);
}

// ---------------- tensor-core GEMM + bias + ReLU (double-buffered) ---------
// C[M,256] = relu(A[M,K](bf16) @ (Wh+Wl)[K,256](bf16 presplit) + b) -> bf16
// BM=128, BN=256, BK=32, 512 threads (16 warps, each 32x64, 2 MMAs/fragment).
// cp.async double-buffering: tile t+1 loads overlap tile t MMAs.
#define TILE_BYTES (10240 + 16896 + 16896)

template <int K>
__launch_bounds__(512)
__global__ void k_gemm_tc(const __nv_bfloat16* __restrict__ A,
                          const __nv_bfloat16* __restrict__ Wh,
                          const __nv_bfloat16* __restrict__ Wl,
                          const float* __restrict__ bias, __nv_bfloat16* __restrict__ Cout) {
    constexpr int NT = K / 32;
    __shared__ __align__(16) unsigned char smraw[2][TILE_BYTES];
    float* scr = (float*)smraw[0];  // epilogue scratch aliases buffer 0

    int tid = threadIdx.x, wid = tid >> 5, lane = tid & 31;
    int m0 = blockIdx.x * 128;
    int wm = wid >> 2, wn = wid & 3;  // warp tile: rows wm*32, cols wn*64

    // per-thread load coordinates
    int ar = tid >> 2, ac8 = (tid & 3) * 8;  // A: 128 rows x 32 k, 16B each
    int gr = m0 + ar;

    wmma::fragment<wmma::accumulator, 16, 16, 16, float> acc[2][4];
#pragma unroll
    for (int mi = 0; mi < 2; mi++)
#pragma unroll
        for (int ni = 0; ni < 4; ni++) wmma::fill_fragment(acc[mi][ni], 0.0f);

    // ---- prefetch tile 0 into buffer 0 ----
    {
        __nv_bfloat16 (*As)[40]  = (__nv_bfloat16(*)[40])(smraw[0]);
        __nv_bfloat16 (*Bh)[264] = (__nv_bfloat16(*)[264])(smraw[0] + 10240);
        __nv_bfloat16 (*Bl)[264] = (__nv_bfloat16(*)[264])(smraw[0] + 10240 + 16896);
        if (gr < NN)
            __pipeline_memcpy_async(&As[ar][ac8], &A[(size_t)gr * K + ac8], 16);
        else
            *(uint4*)&As[ar][ac8] = make_uint4(0u, 0u, 0u, 0u);
#pragma unroll
        for (int it = 0; it < 2; it++) {
            int p = tid + it * 512;
            int r = p >> 5, c8 = (p & 31) * 8;
            __pipeline_memcpy_async(&Bh[r][c8], &Wh[(size_t)r * DH + c8], 16);
            __pipeline_memcpy_async(&Bl[r][c8], &Wl[(size_t)r * DH + c8], 16);
        }
        __pipeline_commit();
    }

    for (int t = 0; t < NT; t++) {
        // ---- prefetch tile t+1 into the other buffer, then wait for tile t ----
        if (t + 1 < NT) {
            int k0 = (t + 1) * 32;
            int nb = (t + 1) & 1;
            __nv_bfloat16 (*As)[40]  = (__nv_bfloat16(*)[40])(smraw[nb]);
            __nv_bfloat16 (*Bh)[264] = (__nv_bfloat16(*)[264])(smraw[nb] + 10240);
            __nv_bfloat16 (*Bl)[264] = (__nv_bfloat16(*)[264])(smraw[nb] + 10240 + 16896);
            if (gr < NN)
                __pipeline_memcpy_async(&As[ar][ac8], &A[(size_t)gr * K + k0 + ac8], 16);
            else
                *(uint4*)&As[ar][ac8] = make_uint4(0u, 0u, 0u, 0u);
#pragma unroll
            for (int it = 0; it < 2; it++) {
                int p = tid + it * 512;
                int r = p >> 5, c8 = (p & 31) * 8;
                __pipeline_memcpy_async(&Bh[r][c8], &Wh[(size_t)(k0 + r) * DH + c8], 16);
                __pipeline_memcpy_async(&Bl[r][c8], &Wl[(size_t)(k0 + r) * DH + c8], 16);
            }
            __pipeline_commit();
            __pipeline_wait_prior(1);   // tile t complete; t+1 may be in flight
        } else {
            __pipeline_wait_prior(0);
        }
        __syncthreads();

        // ---- compute on buffer t&1 ----
        {
            int cb = t & 1;
            __nv_bfloat16 (*As)[40]  = (__nv_bfloat16(*)[40])(smraw[cb]);
            __nv_bfloat16 (*Bh)[264] = (__nv_bfloat16(*)[264])(smraw[cb] + 10240);
            __nv_bfloat16 (*Bl)[264] = (__nv_bfloat16(*)[264])(smraw[cb] + 10240 + 16896);
#pragma unroll
            for (int ks = 0; ks < 2; ks++) {
                wmma::fragment<wmma::matrix_a, 16, 16, 16, __nv_bfloat16, wmma::row_major> ah[2];
#pragma unroll
                for (int mi = 0; mi < 2; mi++)
                    wmma::load_matrix_sync(ah[mi], &As[wm * 32 + mi * 16][ks * 16], 40);
#pragma unroll
                for (int ni = 0; ni < 4; ni++) {
                    wmma::fragment<wmma::matrix_b, 16, 16, 16, __nv_bfloat16, wmma::row_major> bh, bl;
                    wmma::load_matrix_sync(bh, &Bh[ks * 16][wn * 64 + ni * 16], 264);
                    wmma::load_matrix_sync(bl, &Bl[ks * 16][wn * 64 + ni * 16], 264);
#pragma unroll
                    for (int mi = 0; mi < 2; mi++) {
                        wmma::mma_sync(acc[mi][ni], ah[mi], bh, acc[mi][ni]);
                        wmma::mma_sync(acc[mi][ni], ah[mi], bl, acc[mi][ni]);
                    }
                }
            }
        }
        __syncthreads();  // all warps done with buffer t&1 before it's refilled
    }

    // Epilogue: stage 16x16 fragments through per-warp smem, bias+relu, bf16 store.
    float* myscr = scr + wid * 256;
    int er = lane >> 1, ec = (lane & 1) * 8;
#pragma unroll
    for (int mi = 0; mi < 2; mi++) {
#pragma unroll
        for (int ni = 0; ni < 4; ni++) {
            wmma::store_matrix_sync(myscr, acc[mi][ni], 16, wmma::mem_row_major);
            __syncwarp();
            int gm = m0 + wm * 32 + mi * 16 + er;
            int gn = wn * 64 + ni * 16 + ec;
            if (gm < NN) {
                float4 b0 = *(const float4*)&bias[gn + 0];
                float4 b1 = *(const float4*)&bias[gn + 4];
                const float* s = &myscr[er * 16 + ec];
                float o[8];
                o[0] = fmaxf(s[0] + b0.x, 0.f); o[1] = fmaxf(s[1] + b0.y, 0.f);
                o[2] = fmaxf(s[2] + b0.z, 0.f); o[3] = fmaxf(s[3] + b0.w, 0.f);
                o[4] = fmaxf(s[4] + b1.x, 0.f); o[5] = fmaxf(s[5] + b1.y, 0.f);
                o[6] = fmaxf(s[6] + b1.z, 0.f); o[7] = fmaxf(s[7] + b1.w, 0.f);
                *(uint4*)&Cout[(size_t)gm * DH + gn] = pack8(o);
            }
            __syncwarp();
        }
    }
}

// ---------------- pooling (two-stage, bf16 input) ----------------
__global__ void k_bounds(const int* __restrict__ batch) {
    int g = threadIdx.x;
    if (g <= NG) {
        int lo = 0, hi = NN;
        while (lo < hi) {
            int mid = (lo + hi) >> 1;
            if (batch[mid] < g) lo = mid + 1; else hi = mid;
        }
        g_gstart[g] = lo;
    }
}

__launch_bounds__(128)
__global__ void k_pool1(const __nv_bfloat162* __restrict__ h2) {
    int g = blockIdx.x >> 4, chunk = blockIdx.x & (PCH - 1);
    int d = threadIdx.x;  // owns features 2d, 2d+1
    int beg = g_gstart[g], end = g_gstart[g + 1];
    long len = end - beg;
    int c0 = beg + (int)(len * chunk / PCH);
    int c1 = beg + (int)(len * (chunk + 1) / PCH);
    float sx0 = 0.f, sy0 = 0.f, sx1 = 0.f, sy1 = 0.f;
    int i = c0;
    for (; i + 2 <= c1; i += 2) {
        float2 f0 = __bfloat1622float2(h2[(size_t)(i + 0) * 128 + d]);
        float2 f1 = __bfloat1622float2(h2[(size_t)(i + 1) * 128 + d]);
        sx0 += f0.x; sy0 += f0.y;
        sx1 += f1.x; sy1 += f1.y;
    }
    if (i < c1) {
        float2 f0 = __bfloat1622float2(h2[(size_t)i * 128 + d]);
        sx0 += f0.x; sy0 += f0.y;
    }
    g_pp[(size_t)blockIdx.x * DH + 2 * d + 0] = sx0 + sx1;
    g_pp[(size_t)blockIdx.x * DH + 2 * d + 1] = sy0 + sy1;
}

__launch_bounds__(256)
__global__ void k_pool2(float* __restrict__ out) {
    int g = blockIdx.x, d = threadIdx.x;
    float s = 0.f;
#pragma unroll
    for (int c = 0; c < PCH; c++) s += g_pp[(size_t)(g * PCH + c) * DH + d];
    int cnt = g_gstart[g + 1] - g_gstart[g];
    out[g * DH + d] = s / fmaxf((float)cnt, 1.f);
}

// ---------------- launch ----------------
extern "C" void kernel_launch(void* const* d_in, const int* in_sizes, int n_in,
                              void* d_out, int out_size) {
    const float* x     = (const float*)d_in[0];
    const int*   ei    = (const int*)d_in[1];
    const int*   batch = (const int*)d_in[2];
    const float* W1    = (const float*)d_in[3];
    const float* b1    = (const float*)d_in[4];
    const float* W2    = (const float*)d_in[5];
    const float* b2    = (const float*)d_in[6];
    float*       out   = (float*)d_out;

    const int* row = ei;       // edge_index[0] = source
    const int* col = ei + NE;  // edge_index[1] = target

    __nv_bfloat16 *hA, *hB, *x16, *W1h, *W1l, *W2h, *W2l;
    cudaGetSymbolAddress((void**)&hA,  g_hA);
    cudaGetSymbolAddress((void**)&hB,  g_hB);
    cudaGetSymbolAddress((void**)&x16, g_x16);
    cudaGetSymbolAddress((void**)&W1h, g_W1h);
    cudaGetSymbolAddress((void**)&W1l, g_W1l);
    cudaGetSymbolAddress((void**)&W2h, g_W2h);
    cudaGetSymbolAddress((void**)&W2l, g_W2l);

    int nb_nodes = (NN + 255) / 256;
    int nb_edges = (NE + 255) / 256;

    // CSR build + conversions (fully re-run every call: graph-replay safe)
    k_zero_deg<<<nb_nodes, 256>>>();
    k_count<<<nb_edges, 256>>>(col);
    k_scan<<<1, 1024>>>();
    k_dinv<<<nb_nodes, 256>>>();
    k_fill<<<nb_edges, 256>>>(row, col);
    k_bounds<<<1, 128>>>(batch);
    k_cvt_x<<<(NN * DIN / 4 + 255) / 256, 256>>>((const float4*)x, (uint2*)x16);
    k_splitW<<<(DIN * DH + 255) / 256, 256>>>(W1, W1h, W1l, DIN * DH);
    k_splitW<<<(DH * DH + 255) / 256, 256>>>(W2, W2h, W2l, DH * DH);

    int gm = (NN + 127) / 128;  // 782
    // Layer 1: agg(x) [D=128] -> @W1 + b1, relu (agg commutes with linear)
    k_agg1<<<(NN + 3) / 4, 128>>>((const uint2*)x16, (uint2*)hA);
    k_gemm_tc<DIN><<<gm, 512>>>(hA, W1h, W1l, b1, hB);
    // Layer 2: agg(h1) [D=256] -> @W2 + b2, relu
    k_agg2<<<(NN + 3) / 4, 128>>>((const uint4*)hB, (uint4*)hA);
    k_gemm_tc<DH><<<gm, 512>>>(hA, W2h, W2l, b2, hB);
    // Global mean pool (two-stage)
    k_pool1<<<NG * PCH, 128>>>((const __nv_bfloat162*)hB);
    k_pool2<<<NG, 256>>>(out);
}